// round 14
// baseline (speedup 1.0000x reference)
#include <cuda_runtime.h>
#include <cuda_fp16.h>
#include <cstdint>

// ---------------------------------------------------------------------------
// BarrierNet — mma.sync fp16 single-pass, half2 tanh-silu, v14.
//   CTA = 512 threads, 512 rows, four 128-row phases. 2 CTAs/SM.
//   Phase A : layer1 fp32 FFMA2, silu in HALF2 (tanh.approx.f16x2, 1 MUFU
//             per 2 elems), output is directly the fp16x2 STS operand.
//   MMA     : warps 0-7, 32r x 32c tiles, single-pass fp16, fp32 acc.
//   Heads   : half2 silu + f32 dot, quad shfl-reduce, tig-select write.
//   CBF     : warps 8-11 after the barrier.
// ---------------------------------------------------------------------------

typedef unsigned long long u64;
typedef unsigned int u32;

#define SM_XF    0        // fp16 x [128 rows][128 k]  32768
#define SM_WF    32768    // fp16 W2 [64 n][128 k]     16384
#define SM_W1P   49152    // u64[640]  W1 (j,j+1) pairs 5120
#define SM_B1P   54272    // u64[64]   512
#define SM_B2    54784    // f32[64]   256
#define SM_B2H   55040    // u32[32]   half2 (b2[2i],b2[2i+1])  128
#define SM_W31   55168    // f32[64]   256
#define SM_W32   55424    // f32[32]   128
#define SM_SCAL  55552    // f32[4]    16
#define SM_U01   55568    // float2[128] 1024
#define SM_AW    56592    // f32[128]    512
#define SMEM_BYTES 57104

#define H05 0x38003800u   // half2 (0.5, 0.5)

static __device__ __forceinline__ u32 smem_u32(const void* p) {
    u32 a;
    asm("{ .reg .u64 t; cvta.to.shared.u64 t, %1; cvt.u32.u64 %0, t; }"
        : "=r"(a) : "l"(p));
    return a;
}
static __device__ __forceinline__ u64 pk2(float lo, float hi) {
    u64 r; asm("mov.b64 %0, {%1, %2};" : "=l"(r) : "f"(lo), "f"(hi)); return r;
}
static __device__ __forceinline__ void upk2(u64 v, float& lo, float& hi) {
    asm("mov.b64 {%0, %1}, %2;" : "=f"(lo), "=f"(hi) : "l"(v));
}
static __device__ __forceinline__ u64 fma2(u64 a, u64 b, u64 c) {
    u64 d; asm("fma.rn.f32x2 %0, %1, %2, %3;" : "=l"(d) : "l"(a), "l"(b), "l"(c)); return d;
}
static __device__ __forceinline__ u64 dup2(float w) { return pk2(w, w); }

static __device__ __forceinline__ float tanh_ap(float x) {
    float t; asm("tanh.approx.f32 %0, %1;" : "=f"(t) : "f"(x)); return t;
}
static __device__ __forceinline__ float fast_silu(float z) {
    return 0.5f * z * (1.0f + tanh_ap(0.5f * z));
}
static __device__ __forceinline__ float fast_sigmoid(float z) {
    return 0.5f * (1.0f + tanh_ap(0.5f * z));
}
// ---- half2 helpers ----
static __device__ __forceinline__ u32 h2_tanh(u32 x) {
    u32 d; asm("tanh.approx.f16x2 %0, %1;" : "=r"(d) : "r"(x)); return d;
}
static __device__ __forceinline__ u32 h2_mul(u32 a, u32 b) {
    u32 d; asm("mul.rn.f16x2 %0, %1, %2;" : "=r"(d) : "r"(a), "r"(b)); return d;
}
static __device__ __forceinline__ u32 h2_fma(u32 a, u32 b, u32 c) {
    u32 d; asm("fma.rn.f16x2 %0, %1, %2, %3;" : "=r"(d) : "r"(a), "r"(b), "r"(c)); return d;
}
static __device__ __forceinline__ u32 h2_add(u32 a, u32 b) {
    u32 d; asm("add.rn.f16x2 %0, %1, %2;" : "=r"(d) : "r"(a), "r"(b)); return d;
}
// silu on a half2: s = z * (0.5 + 0.5*tanh(0.5*z))
static __device__ __forceinline__ u32 h2_silu(u32 zh) {
    u32 t = h2_tanh(h2_mul(zh, H05));
    return h2_mul(zh, h2_fma(t, H05, H05));
}
// pack two floats to fp16x2 (lower 16 bits = s0)
static __device__ __forceinline__ u32 cvt_f16x2(float s1, float s0) {
    u32 d; asm("cvt.rn.f16x2.f32 %0, %1, %2;" : "=r"(d) : "f"(s1), "f"(s0));
    return d;
}
static __device__ __forceinline__ void ldsm4(u32* r, u32 addr) {
    asm volatile("ldmatrix.sync.aligned.m8n8.x4.shared.b16 {%0,%1,%2,%3}, [%4];"
        : "=r"(r[0]), "=r"(r[1]), "=r"(r[2]), "=r"(r[3]) : "r"(addr));
}
static __device__ __forceinline__ void mma_f16(float* d, const u32* a, u32 b0, u32 b1) {
    asm volatile("mma.sync.aligned.m16n8k16.row.col.f32.f16.f16.f32 "
        "{%0,%1,%2,%3}, {%4,%5,%6,%7}, {%8,%9}, {%0,%1,%2,%3};"
        : "+f"(d[0]), "+f"(d[1]), "+f"(d[2]), "+f"(d[3])
        : "r"(a[0]), "r"(a[1]), "r"(a[2]), "r"(a[3]), "r"(b0), "r"(b1));
}

__global__ void __launch_bounds__(512, 2)
barriernet_kernel(const float* __restrict__ obs,
                  const float* __restrict__ W1,  const float* __restrict__ b1,
                  const float* __restrict__ W21, const float* __restrict__ b21,
                  const float* __restrict__ W22, const float* __restrict__ b22,
                  const float* __restrict__ W31, const float* __restrict__ b31,
                  const float* __restrict__ W32, const float* __restrict__ b32,
                  float* __restrict__ out, int B)
{
    extern __shared__ char smc[];
    const u32 smb = smem_u32(smc);
    const int tid = threadIdx.x;

    u64*    w1p  = reinterpret_cast<u64*>(smc + SM_W1P);
    u64*    b1p  = reinterpret_cast<u64*>(smc + SM_B1P);
    float*  b2f  = reinterpret_cast<float*>(smc + SM_B2);
    u32*    b2h  = reinterpret_cast<u32*>(smc + SM_B2H);
    float*  w31f = reinterpret_cast<float*>(smc + SM_W31);
    float*  w32f = reinterpret_cast<float*>(smc + SM_W32);
    float*  scal = reinterpret_cast<float*>(smc + SM_SCAL);
    float2* u01  = reinterpret_cast<float2*>(smc + SM_U01);
    float*  awb  = reinterpret_cast<float*>(smc + SM_AW);

    // ------------------------------ staging ------------------------------
    for (int i = tid; i < 640; i += 512) {
        int jp = i / 10, f = i - jp * 10;
        w1p[i] = pk2(W1[(2 * jp) * 10 + f], W1[(2 * jp + 1) * 10 + f]);
    }
    if (tid < 64) {
        b1p[tid]  = pk2(b1[2 * tid], b1[2 * tid + 1]);
        b2f[tid]  = (tid < 32) ? b21[tid] : b22[tid - 32];
        w31f[tid] = W31[tid];                       // [2][32] row-major
    }
    if (tid < 32) {
        w32f[tid] = W32[tid];
        float e0 = (tid < 16) ? b21[2 * tid]     : b22[2 * (tid - 16)];
        float e1 = (tid < 16) ? b21[2 * tid + 1] : b22[2 * (tid - 16) + 1];
        b2h[tid] = cvt_f16x2(e1, e0);
    }
    if (tid == 0) { scal[0] = b31[0]; scal[1] = b31[1]; scal[2] = b32[0]; }

    // W2 = [W21 ; W22] fp16, [n][k] 256B rows, XOR swizzle
    for (int i = tid; i < 4096; i += 512) {
        int n = i >> 6, kp = i & 63;                // elems k = 2kp, 2kp+1
        const float* src = (n < 32) ? (W21 + n * 128 + 2 * kp)
                                    : (W22 + (n - 32) * 128 + 2 * kp);
        float2 w = *reinterpret_cast<const float2*>(src);
        u32 off = (u32)(n * 256) + (((u32)(4 * kp)) ^ ((u32)(n & 7) << 4));
        *reinterpret_cast<u32*>(smc + SM_WF + off) = cvt_f16x2(w.y, w.x);
    }
    __syncthreads();

    const long long row_base = (long long)blockIdx.x * 512;

    // -------- phase-A mapping --------
    const int prow = tid & 127;
    const int jq   = tid >> 7;          // 16 j-pairs starting at jq*16

    // -------- mma mapping (warps 0-7): 32 rows x 32 cols --------
    const int wid = tid >> 5, lane = tid & 31;
    const int gid = lane >> 2, tig = lane & 3;
    const int g8  = lane >> 3, r8 = lane & 7;
    const int mg  = wid & 3;            // rows mg*32 .. mg*32+31
    const int nh  = wid >> 2;           // n-half (0: u cols, 1: alpha cols)
    const u32 swz    = (u32)r8 << 4;
    const u32 a_koff = (u32)((g8 >> 1) << 4);
    const int arow0  = mg * 32 + ((g8 & 1) << 3) + r8;
    const u32 aF0 = smb + SM_XF + (u32)arow0 * 256;
    const u32 aF1 = aF0 + 16 * 256;
    const u32 b_noff = (u32)(((g8 >> 1) << 3) + r8);
    const u32 b_koff = (u32)((g8 & 1) << 4);
    u32 bFb[2];
    #pragma unroll
    for (int g = 0; g < 2; g++) {
        u32 n = (u32)(nh * 32 + g * 16) + b_noff;
        bFb[g] = smb + SM_WF + n * 256;
    }

    #pragma unroll 1
    for (int ph = 0; ph < 4; ph++) {
        // ======================= Phase A (128 rows, all warps) =======================
        {
            const long long grow = row_base + ph * 128 + prow;
            u64 od[10];
            if (grow < B) {
                const float2* q = reinterpret_cast<const float2*>(obs + grow * 10);
                #pragma unroll
                for (int f = 0; f < 5; f++) {
                    float2 v = q[f];
                    od[2 * f]     = dup2(v.x);
                    od[2 * f + 1] = dup2(v.y);
                }
            } else {
                #pragma unroll
                for (int f = 0; f < 10; f++) od[f] = 0ull;
            }
            const u32 swr = ((u32)(prow & 7)) << 4;
            #pragma unroll 1
            for (int blk = 0; blk < 4; blk++) {
                u32 xq[4];
                #pragma unroll
                for (int q = 0; q < 4; q++) {
                    const int jp = jq * 16 + blk * 4 + q;
                    const ulonglong2* wv =
                        reinterpret_cast<const ulonglong2*>(w1p + jp * 10);
                    ulonglong2 w01 = wv[0], w23 = wv[1], w45 = wv[2],
                               w67 = wv[3], w89 = wv[4];
                    u64 z = b1p[jp];
                    z = fma2(od[0], w01.x, z); z = fma2(od[1], w01.y, z);
                    z = fma2(od[2], w23.x, z); z = fma2(od[3], w23.y, z);
                    z = fma2(od[4], w45.x, z); z = fma2(od[5], w45.y, z);
                    z = fma2(od[6], w67.x, z); z = fma2(od[7], w67.y, z);
                    z = fma2(od[8], w89.x, z); z = fma2(od[9], w89.y, z);
                    float z0, z1; upk2(z, z0, z1);
                    xq[q] = h2_silu(cvt_f16x2(z1, z0));
                }
                const u32 kb  = (u32)(jq * 64 + blk * 16);
                const u32 off = (u32)prow * 256 + (kb ^ swr);
                *reinterpret_cast<uint4*>(smc + SM_XF + off) =
                    make_uint4(xq[0], xq[1], xq[2], xq[3]);
            }
        }
        __syncthreads();

        // ======================= MMA: warps 0-7, 32r x 32c, single pass ===========
        if (wid < 8) {
            float acc[2][4][4];
            #pragma unroll
            for (int m = 0; m < 2; m++)
                #pragma unroll
                for (int nt = 0; nt < 4; nt++)
                    #pragma unroll
                    for (int c = 0; c < 4; c++) acc[m][nt][c] = 0.f;

            #pragma unroll 2
            for (int ks = 0; ks < 8; ks++) {
                const u32 kbyte = (u32)(32 * ks);
                const u32 ka = (kbyte + a_koff) ^ swz;
                const u32 kb = (kbyte + b_koff) ^ swz;
                u32 a0[4], a1[4], bf0[4], bf1[4];
                ldsm4(a0, aF0 + ka);
                ldsm4(a1, aF1 + ka);
                ldsm4(bf0, bFb[0] + kb);
                ldsm4(bf1, bFb[1] + kb);
                #pragma unroll
                for (int nt = 0; nt < 4; nt++) {
                    u32 b0 = (nt < 2 ? bf0 : bf1)[(nt & 1) * 2];
                    u32 b1v = (nt < 2 ? bf0 : bf1)[(nt & 1) * 2 + 1];
                    mma_f16(acc[0][nt], a0, b0, b1v);
                    mma_f16(acc[1][nt], a1, b0, b1v);
                }
            }

            // ---- heads partials: half2 silu + f32 dot, quad-reduce ----
            float p0[4] = {0.f, 0.f, 0.f, 0.f};
            float p1[4] = {0.f, 0.f, 0.f, 0.f};
            #pragma unroll
            for (int m = 0; m < 2; m++)
                #pragma unroll
                for (int nt = 0; nt < 4; nt++) {
                    const int col = nh * 32 + nt * 8 + 2 * tig;   // even col
                    const u32 bh = b2h[col >> 1];
                    // rows: lo = (gid), hi = (gid+8)
                    u32 zlo = h2_add(cvt_f16x2(acc[m][nt][1], acc[m][nt][0]), bh);
                    u32 zhi = h2_add(cvt_f16x2(acc[m][nt][3], acc[m][nt][2]), bh);
                    u32 slo = h2_silu(zlo);
                    u32 shi = h2_silu(zhi);
                    float2 flo = __half22float2(*reinterpret_cast<__half2*>(&slo));
                    float2 fhi = __half22float2(*reinterpret_cast<__half2*>(&shi));
                    if (nh == 0) {
                        const float wA0 = w31f[col], wA1 = w31f[col + 1];
                        const float wB0 = w31f[32 + col], wB1 = w31f[32 + col + 1];
                        p0[2 * m]     += flo.x * wA0 + flo.y * wA1;
                        p1[2 * m]     += flo.x * wB0 + flo.y * wB1;
                        p0[2 * m + 1] += fhi.x * wA0 + fhi.y * wA1;
                        p1[2 * m + 1] += fhi.x * wB0 + fhi.y * wB1;
                    } else {
                        const float wC0 = w32f[col - 32], wC1 = w32f[col - 31];
                        p0[2 * m]     += flo.x * wC0 + flo.y * wC1;
                        p0[2 * m + 1] += fhi.x * wC0 + fhi.y * wC1;
                    }
                }
            #pragma unroll
            for (int i = 0; i < 4; i++) {
                p0[i] += __shfl_xor_sync(0xFFFFFFFFu, p0[i], 1);
                p0[i] += __shfl_xor_sync(0xFFFFFFFFu, p0[i], 2);
                if (nh == 0) {
                    p1[i] += __shfl_xor_sync(0xFFFFFFFFu, p1[i], 1);
                    p1[i] += __shfl_xor_sync(0xFFFFFFFFu, p1[i], 2);
                }
            }
            {
                const int row = mg * 32 + gid + tig * 8;
                const float s0 = (tig == 0) ? p0[0] : (tig == 1) ? p0[1]
                               : (tig == 2) ? p0[2] : p0[3];
                if (nh == 0) {
                    const float s1 = (tig == 0) ? p1[0] : (tig == 1) ? p1[1]
                                   : (tig == 2) ? p1[2] : p1[3];
                    u01[row] = make_float2(s0, s1);
                } else {
                    awb[row] = s0;
                }
            }
        }
        __syncthreads();

        // ======================= CBF + store (warps 8-11) =======================
        if (tid >= 256 && tid < 384) {
            const int r = tid - 256;
            const long long grow = row_base + ph * 128 + r;
            if (grow < B) {
                float2 uv = u01[r];
                const float u0 = uv.x + scal[0];
                const float u1 = uv.y + scal[1];
                const float aw = awb[r] + scal[2];
                const float2* pp = reinterpret_cast<const float2*>(obs + grow * 10 + 6);
                const float2 rv = pp[0], vv = pp[1];
                const float alpha   = 4.0f * fast_sigmoid(aw);
                const float barrier = rv.x * rv.x + rv.y * rv.y - 0.64f;
                const float lf      = -2.0f * (rv.x * vv.x + rv.y * vv.y);
                const float Gx = -2.0f * rv.x, Gy = -2.0f * rv.y;
                const float hh   = lf + alpha * barrier;
                const float gg   = Gx * Gx + Gy * Gy;
                const float viol = Gx * u0 + Gy * u1 - hh;
                const float lam  = (gg > 0.0f)
                    ? __fdividef(fmaxf(viol, 0.0f), fmaxf(gg, 1e-12f))
                    : 0.0f;
                reinterpret_cast<float2*>(out)[grow] =
                    make_float2(u0 - lam * Gx, u1 - lam * Gy);
            }
        }
    }
}

extern "C" void kernel_launch(void* const* d_in, const int* in_sizes, int n_in,
                              void* d_out, int out_size)
{
    const float* obs = (const float*)d_in[0];
    const float* W1  = (const float*)d_in[1];
    const float* b1  = (const float*)d_in[2];
    const float* W21 = (const float*)d_in[3];
    const float* b21 = (const float*)d_in[4];
    const float* W22 = (const float*)d_in[5];
    const float* b22 = (const float*)d_in[6];
    const float* W31 = (const float*)d_in[7];
    const float* b31 = (const float*)d_in[8];
    const float* W32 = (const float*)d_in[9];
    const float* b32 = (const float*)d_in[10];
    float* out = (float*)d_out;

    int B = in_sizes[0] / 10;

    cudaFuncSetAttribute(barriernet_kernel,
                         cudaFuncAttributeMaxDynamicSharedMemorySize, SMEM_BYTES);

    int blocks = (B + 511) / 512;
    barriernet_kernel<<<blocks, 512, SMEM_BYTES>>>(
        obs, W1, b1, W21, b21, W22, b22, W31, b31, W32, b32, out, B);
}

// round 15
// speedup vs baseline: 1.3769x; 1.3769x over previous
#include <cuda_runtime.h>
#include <cuda_fp16.h>
#include <cstdint>

// ---------------------------------------------------------------------------
// BarrierNet — all-MMA fp16, v15.
//   CTA = 512 threads, 512 rows, four 128-row phases, 2 CTAs/SM.
//   Layer1 : fp16 MMA (K=16, obs zero-padded), warps 0-7, 32r x 64n in two
//            halves; bias + f32 tanh-silu on D frags; repack fp16x2 -> X tile.
//   Layer2 : fp16 MMA warps 0-7, 32r x 32c, single pass, fp32 acc.
//   obs    : staged one phase ahead by warps 12-15 (overlapped LDG).
//   CBF    : warps 8-11, for phase ph-1, overlapped with next layer-1 MMA.
// ---------------------------------------------------------------------------

typedef unsigned long long u64;
typedef unsigned int u32;

#define SM_XF    0        // fp16 X [128 rows][128 j] 256B rows, swizzled  32768
#define SM_WF    32768    // fp16 W2 [64 n][128 j]                        16384
#define SM_A1    49152    // 2 x (128 rows x 48B) obs fp16 K=16 padded    12288
#define SM_W1H   61440    // fp16 W1 [128 n][16 k] stride 48B              6144
#define SM_B1F   67584    // f32[128]                                      512
#define SM_W31   68096    // f32[64]                                       256
#define SM_W32   68352    // f32[32]                                       128
#define SM_SCAL  68480    // f32[4]                                         16
#define SM_B2F   68496    // f32[64]                                       256
#define SM_U01   68752    // float2[2][128]                               2048
#define SM_AW    70800    // f32[2][128]                                  1024
#define SMEM_BYTES 71824

static __device__ __forceinline__ u32 smem_u32(const void* p) {
    u32 a;
    asm("{ .reg .u64 t; cvta.to.shared.u64 t, %1; cvt.u32.u64 %0, t; }"
        : "=r"(a) : "l"(p));
    return a;
}
static __device__ __forceinline__ float tanh_ap(float x) {
    float t; asm("tanh.approx.f32 %0, %1;" : "=f"(t) : "f"(x)); return t;
}
static __device__ __forceinline__ float fast_silu(float z) {
    return 0.5f * z * (1.0f + tanh_ap(0.5f * z));
}
static __device__ __forceinline__ float fast_sigmoid(float z) {
    return 0.5f * (1.0f + tanh_ap(0.5f * z));
}
static __device__ __forceinline__ u32 cvt_f16x2(float s1, float s0) {
    u32 d; asm("cvt.rn.f16x2.f32 %0, %1, %2;" : "=r"(d) : "f"(s1), "f"(s0));
    return d;
}
static __device__ __forceinline__ void ldsm4(u32* r, u32 addr) {
    asm volatile("ldmatrix.sync.aligned.m8n8.x4.shared.b16 {%0,%1,%2,%3}, [%4];"
        : "=r"(r[0]), "=r"(r[1]), "=r"(r[2]), "=r"(r[3]) : "r"(addr));
}
static __device__ __forceinline__ void sts32(u32 addr, u32 v) {
    asm volatile("st.shared.b32 [%0], %1;" :: "r"(addr), "r"(v) : "memory");
}
static __device__ __forceinline__ void mma_f16(float* d, const u32* a, u32 b0, u32 b1) {
    asm volatile("mma.sync.aligned.m16n8k16.row.col.f32.f16.f16.f32 "
        "{%0,%1,%2,%3}, {%4,%5,%6,%7}, {%8,%9}, {%0,%1,%2,%3};"
        : "+f"(d[0]), "+f"(d[1]), "+f"(d[2]), "+f"(d[3])
        : "r"(a[0]), "r"(a[1]), "r"(a[2]), "r"(a[3]), "r"(b0), "r"(b1));
}

__global__ void __launch_bounds__(512, 2)
barriernet_kernel(const float* __restrict__ obs,
                  const float* __restrict__ W1,  const float* __restrict__ b1,
                  const float* __restrict__ W21, const float* __restrict__ b21,
                  const float* __restrict__ W22, const float* __restrict__ b22,
                  const float* __restrict__ W31, const float* __restrict__ b31,
                  const float* __restrict__ W32, const float* __restrict__ b32,
                  float* __restrict__ out, int B)
{
    extern __shared__ char smc[];
    const u32 smb = smem_u32(smc);
    const int tid = threadIdx.x;

    float*  b1f  = reinterpret_cast<float*>(smc + SM_B1F);
    float*  b2f  = reinterpret_cast<float*>(smc + SM_B2F);
    float*  w31f = reinterpret_cast<float*>(smc + SM_W31);
    float*  w32f = reinterpret_cast<float*>(smc + SM_W32);
    float*  scal = reinterpret_cast<float*>(smc + SM_SCAL);

    const long long row_base = (long long)blockIdx.x * 512;

    // ------------------------------ staging ------------------------------
    // W1 fp16 tile [128 n][16 k], stride 48B, k>=10 zero
    for (int i = tid; i < 2048; i += 512) {
        int n = i >> 4, k = i & 15;
        __half v = (k < 10) ? __float2half(W1[n * 10 + k]) : __half(0.f);
        *reinterpret_cast<__half*>(smc + SM_W1H + n * 48 + k * 2) = v;
    }
    if (tid < 128) b1f[tid] = b1[tid];
    if (tid < 64) {
        b2f[tid]  = (tid < 32) ? b21[tid] : b22[tid - 32];
        w31f[tid] = W31[tid];                       // [2][32] row-major
    }
    if (tid < 32) w32f[tid] = W32[tid];
    if (tid == 0) { scal[0] = b31[0]; scal[1] = b31[1]; scal[2] = b32[0]; }

    // W2 = [W21 ; W22] fp16, [n][k] 256B rows, XOR swizzle
    for (int i = tid; i < 4096; i += 512) {
        int n = i >> 6, kp = i & 63;
        const float* src = (n < 32) ? (W21 + n * 128 + 2 * kp)
                                    : (W22 + (n - 32) * 128 + 2 * kp);
        float2 w = *reinterpret_cast<const float2*>(src);
        u32 off = (u32)(n * 256) + (((u32)(4 * kp)) ^ ((u32)(n & 7) << 4));
        *reinterpret_cast<u32*>(smc + SM_WF + off) = cvt_f16x2(w.y, w.x);
    }

    // prologue: stage obs phase 0 -> A1[0] (threads 384-511)
    if (tid >= 384) {
        const int r = tid - 384;
        const long long grow = row_base + r;
        u32 h[8];
        if (grow < B) {
            const float2* q = reinterpret_cast<const float2*>(obs + grow * 10);
            float2 v0 = q[0], v1 = q[1], v2 = q[2], v3 = q[3], v4 = q[4];
            h[0] = cvt_f16x2(v0.y, v0.x); h[1] = cvt_f16x2(v1.y, v1.x);
            h[2] = cvt_f16x2(v2.y, v2.x); h[3] = cvt_f16x2(v3.y, v3.x);
            h[4] = cvt_f16x2(v4.y, v4.x);
        } else { h[0] = h[1] = h[2] = h[3] = h[4] = 0u; }
        h[5] = h[6] = h[7] = 0u;
        char* a1 = smc + SM_A1 + r * 48;
        *reinterpret_cast<uint4*>(a1)      = make_uint4(h[0], h[1], h[2], h[3]);
        *reinterpret_cast<uint4*>(a1 + 16) = make_uint4(h[4], h[5], h[6], h[7]);
    }
    __syncthreads();

    // -------- common warp/lane mapping --------
    const int wid = tid >> 5, lane = tid & 31;
    const int gid = lane >> 2, tig = lane & 3;
    const int g8  = lane >> 3, r8 = lane & 7;
    const int mg  = wid & 3;            // rows mg*32 .. mg*32+31
    const int nh  = wid >> 2;           // n-half

    // layer-1 MMA addressing (stride-48 tiles)
    const int arow1  = mg * 32 + ((g8 & 1) << 3) + r8;
    const u32 aOff1  = (u32)arow1 * 48 + ((u32)(g8 >> 1) << 4);
    const u32 w1base = smb + SM_W1H
                     + (u32)((((g8 >> 1) << 3) + r8) * 48) + ((u32)(g8 & 1) << 4);

    // layer-2 MMA addressing (256B swizzled tiles)
    const u32 swz    = (u32)r8 << 4;
    const u32 a_koff = (u32)((g8 >> 1) << 4);
    const int arow0  = mg * 32 + ((g8 & 1) << 3) + r8;
    const u32 aF0 = smb + SM_XF + (u32)arow0 * 256;
    const u32 aF1 = aF0 + 16 * 256;
    const u32 b_noff = (u32)(((g8 >> 1) << 3) + r8);
    const u32 b_koff = (u32)((g8 & 1) << 4);
    u32 bFb[2];
    #pragma unroll
    for (int g = 0; g < 2; g++) {
        u32 n = (u32)(nh * 32 + g * 16) + b_noff;
        bFb[g] = smb + SM_WF + n * 256;
    }

    #pragma unroll 1
    for (int ph = 0; ph < 4; ph++) {
        // ============ STEP 1: layer-1 MMA (w0-7) | CBF ph-1 (w8-11) | stage obs ph+1 (w12-15)
        if (wid < 8) {
            const u32 a1b = smb + SM_A1 + (u32)((ph & 1) * 6144);
            u32 af0[4], af1[4];
            ldsm4(af0, a1b + aOff1);
            ldsm4(af1, a1b + aOff1 + 16 * 48);
            #pragma unroll
            for (int hf = 0; hf < 2; hf++) {
                float acc[2][4][4];
                #pragma unroll
                for (int m = 0; m < 2; m++)
                    #pragma unroll
                    for (int nt = 0; nt < 4; nt++)
                        #pragma unroll
                        for (int c = 0; c < 4; c++) acc[m][nt][c] = 0.f;
                u32 bf[2][4];
                ldsm4(bf[0], w1base + (u32)((nh * 64 + hf * 32)      * 48));
                ldsm4(bf[1], w1base + (u32)((nh * 64 + hf * 32 + 16) * 48));
                #pragma unroll
                for (int nt = 0; nt < 4; nt++) {
                    u32 b0  = bf[nt >> 1][(nt & 1) * 2];
                    u32 b1v = bf[nt >> 1][(nt & 1) * 2 + 1];
                    mma_f16(acc[0][nt], af0, b0, b1v);
                    mma_f16(acc[1][nt], af1, b0, b1v);
                }
                // bias + silu + repack into X tile
                #pragma unroll
                for (int m = 0; m < 2; m++) {
                    const int r0 = mg * 32 + m * 16 + gid;
                    const u32 swr = ((u32)(r0 & 7)) << 4;
                    const u32 xb0 = smb + SM_XF + (u32)r0 * 256;
                    #pragma unroll
                    for (int nt = 0; nt < 4; nt++) {
                        const int col = nh * 64 + hf * 32 + nt * 8 + 2 * tig;
                        const float2 bb = *reinterpret_cast<const float2*>(b1f + col);
                        u32 v0 = cvt_f16x2(fast_silu(acc[m][nt][1] + bb.y),
                                           fast_silu(acc[m][nt][0] + bb.x));
                        u32 v1 = cvt_f16x2(fast_silu(acc[m][nt][3] + bb.y),
                                           fast_silu(acc[m][nt][2] + bb.x));
                        const u32 co = ((u32)(2 * col)) ^ swr;
                        sts32(xb0 + co, v0);
                        sts32(xb0 + 8 * 256 + co, v1);
                    }
                }
            }
        } else if (wid < 12) {
            if (ph > 0) {
                const int r = tid - 256;
                const long long grow = row_base + (ph - 1) * 128 + r;
                if (grow < B) {
                    const float2* u01p = reinterpret_cast<const float2*>(
                        smc + SM_U01 + ((ph - 1) & 1) * 1024);
                    const float* awp = reinterpret_cast<const float*>(
                        smc + SM_AW + ((ph - 1) & 1) * 512);
                    float2 uv = u01p[r];
                    const float u0 = uv.x + scal[0];
                    const float u1 = uv.y + scal[1];
                    const float aw = awp[r] + scal[2];
                    const float2* pp = reinterpret_cast<const float2*>(obs + grow * 10 + 6);
                    const float2 rv = pp[0], vv = pp[1];
                    const float alpha   = 4.0f * fast_sigmoid(aw);
                    const float barrier = rv.x * rv.x + rv.y * rv.y - 0.64f;
                    const float lf      = -2.0f * (rv.x * vv.x + rv.y * vv.y);
                    const float Gx = -2.0f * rv.x, Gy = -2.0f * rv.y;
                    const float hh   = lf + alpha * barrier;
                    const float gg   = Gx * Gx + Gy * Gy;
                    const float viol = Gx * u0 + Gy * u1 - hh;
                    const float lam  = (gg > 0.0f)
                        ? __fdividef(fmaxf(viol, 0.0f), fmaxf(gg, 1e-12f))
                        : 0.0f;
                    reinterpret_cast<float2*>(out)[grow] =
                        make_float2(u0 - lam * Gx, u1 - lam * Gy);
                }
            }
        } else {
            if (ph < 3) {
                const int r = tid - 384;
                const long long grow = row_base + (ph + 1) * 128 + r;
                u32 h[8];
                if (grow < B) {
                    const float2* q = reinterpret_cast<const float2*>(obs + grow * 10);
                    float2 v0 = q[0], v1 = q[1], v2 = q[2], v3 = q[3], v4 = q[4];
                    h[0] = cvt_f16x2(v0.y, v0.x); h[1] = cvt_f16x2(v1.y, v1.x);
                    h[2] = cvt_f16x2(v2.y, v2.x); h[3] = cvt_f16x2(v3.y, v3.x);
                    h[4] = cvt_f16x2(v4.y, v4.x);
                } else { h[0] = h[1] = h[2] = h[3] = h[4] = 0u; }
                h[5] = h[6] = h[7] = 0u;
                char* a1 = smc + SM_A1 + ((ph + 1) & 1) * 6144 + r * 48;
                *reinterpret_cast<uint4*>(a1)      = make_uint4(h[0], h[1], h[2], h[3]);
                *reinterpret_cast<uint4*>(a1 + 16) = make_uint4(h[4], h[5], h[6], h[7]);
            }
        }
        __syncthreads();

        // ============ STEP 2: layer-2 MMA + heads partials (w0-7) ============
        if (wid < 8) {
            float acc[2][4][4];
            #pragma unroll
            for (int m = 0; m < 2; m++)
                #pragma unroll
                for (int nt = 0; nt < 4; nt++)
                    #pragma unroll
                    for (int c = 0; c < 4; c++) acc[m][nt][c] = 0.f;

            #pragma unroll 2
            for (int ks = 0; ks < 8; ks++) {
                const u32 kbyte = (u32)(32 * ks);
                const u32 ka = (kbyte + a_koff) ^ swz;
                const u32 kb = (kbyte + b_koff) ^ swz;
                u32 a0[4], a1v[4], bf0[4], bf1[4];
                ldsm4(a0, aF0 + ka);
                ldsm4(a1v, aF1 + ka);
                ldsm4(bf0, bFb[0] + kb);
                ldsm4(bf1, bFb[1] + kb);
                #pragma unroll
                for (int nt = 0; nt < 4; nt++) {
                    u32 b0 = (nt < 2 ? bf0 : bf1)[(nt & 1) * 2];
                    u32 b1v = (nt < 2 ? bf0 : bf1)[(nt & 1) * 2 + 1];
                    mma_f16(acc[0][nt], a0, b0, b1v);
                    mma_f16(acc[1][nt], a1v, b0, b1v);
                }
            }

            float p0[4] = {0.f, 0.f, 0.f, 0.f};
            float p1[4] = {0.f, 0.f, 0.f, 0.f};
            #pragma unroll
            for (int m = 0; m < 2; m++)
                #pragma unroll
                for (int nt = 0; nt < 4; nt++)
                    #pragma unroll
                    for (int c = 0; c < 2; c++) {
                        const int col = nh * 32 + nt * 8 + 2 * tig + c;
                        const float bias = b2f[col];
                        const float vlo = fast_silu(acc[m][nt][c] + bias);
                        const float vhi = fast_silu(acc[m][nt][2 + c] + bias);
                        if (nh == 0) {
                            const float wA = w31f[col], wB = w31f[32 + col];
                            p0[2 * m]     += vlo * wA; p1[2 * m]     += vlo * wB;
                            p0[2 * m + 1] += vhi * wA; p1[2 * m + 1] += vhi * wB;
                        } else {
                            const float wC = w32f[col - 32];
                            p0[2 * m]     += vlo * wC;
                            p0[2 * m + 1] += vhi * wC;
                        }
                    }
            #pragma unroll
            for (int i = 0; i < 4; i++) {
                p0[i] += __shfl_xor_sync(0xFFFFFFFFu, p0[i], 1);
                p0[i] += __shfl_xor_sync(0xFFFFFFFFu, p0[i], 2);
                if (nh == 0) {
                    p1[i] += __shfl_xor_sync(0xFFFFFFFFu, p1[i], 1);
                    p1[i] += __shfl_xor_sync(0xFFFFFFFFu, p1[i], 2);
                }
            }
            {
                const int row = mg * 32 + gid + tig * 8;
                const float s0 = (tig == 0) ? p0[0] : (tig == 1) ? p0[1]
                               : (tig == 2) ? p0[2] : p0[3];
                if (nh == 0) {
                    const float s1 = (tig == 0) ? p1[0] : (tig == 1) ? p1[1]
                                   : (tig == 2) ? p1[2] : p1[3];
                    reinterpret_cast<float2*>(smc + SM_U01 + (ph & 1) * 1024)[row] =
                        make_float2(s0, s1);
                } else {
                    reinterpret_cast<float*>(smc + SM_AW + (ph & 1) * 512)[row] = s0;
                }
            }
        }
        __syncthreads();
    }

    // ============ tail: CBF for phase 3 ============
    if (tid < 128) {
        const int r = tid;
        const long long grow = row_base + 3 * 128 + r;
        if (grow < B) {
            const float2* u01p = reinterpret_cast<const float2*>(smc + SM_U01 + 1024);
            const float* awp = reinterpret_cast<const float*>(smc + SM_AW + 512);
            float2 uv = u01p[r];
            const float u0 = uv.x + scal[0];
            const float u1 = uv.y + scal[1];
            const float aw = awp[r] + scal[2];
            const float2* pp = reinterpret_cast<const float2*>(obs + grow * 10 + 6);
            const float2 rv = pp[0], vv = pp[1];
            const float alpha   = 4.0f * fast_sigmoid(aw);
            const float barrier = rv.x * rv.x + rv.y * rv.y - 0.64f;
            const float lf      = -2.0f * (rv.x * vv.x + rv.y * vv.y);
            const float Gx = -2.0f * rv.x, Gy = -2.0f * rv.y;
            const float hh   = lf + alpha * barrier;
            const float gg   = Gx * Gx + Gy * Gy;
            const float viol = Gx * u0 + Gy * u1 - hh;
            const float lam  = (gg > 0.0f)
                ? __fdividef(fmaxf(viol, 0.0f), fmaxf(gg, 1e-12f))
                : 0.0f;
            reinterpret_cast<float2*>(out)[grow] =
                make_float2(u0 - lam * Gx, u1 - lam * Gy);
        }
    }
}

extern "C" void kernel_launch(void* const* d_in, const int* in_sizes, int n_in,
                              void* d_out, int out_size)
{
    const float* obs = (const float*)d_in[0];
    const float* W1  = (const float*)d_in[1];
    const float* b1  = (const float*)d_in[2];
    const float* W21 = (const float*)d_in[3];
    const float* b21 = (const float*)d_in[4];
    const float* W22 = (const float*)d_in[5];
    const float* b22 = (const float*)d_in[6];
    const float* W31 = (const float*)d_in[7];
    const float* b31 = (const float*)d_in[8];
    const float* W32 = (const float*)d_in[9];
    const float* b32 = (const float*)d_in[10];
    float* out = (float*)d_out;

    int B = in_sizes[0] / 10;

    cudaFuncSetAttribute(barriernet_kernel,
                         cudaFuncAttributeMaxDynamicSharedMemorySize, SMEM_BYTES);

    int blocks = (B + 511) / 512;
    barriernet_kernel<<<blocks, 512, SMEM_BYTES>>>(
        obs, W1, b1, W21, b21, W22, b22, W31, b31, W32, b32, out, B);
}